// round 13
// baseline (speedup 1.0000x reference)
#include <cuda_runtime.h>
#include <cuda_fp16.h>
#include <cstdint>

#define N_NODE 50000
#define N_EDGE 800000
#define D_FEAT 64
#define DEPTH  3
#define M_TERMS 11
#define NF (N_NODE * D_FEAT)   // 3,200,000
#define SCAN_BS 1024
#define NBLK_SCAN ((N_NODE + SCAN_BS - 1) / SCAN_BS)   // 49
#define EQ4 (N_EDGE / 4)       // 200,000

// ---------------- scratch (device globals; zero-initialized at load) ----------------
__device__ __half g_yh[2 * NF];           // S^1 x, S^2 x (fp16: gather + epilogue source)
__device__ __half g_xh[NF];               // fp16 copy of x
__device__ float  g_dinv[N_NODE];
__device__ int    g_cnt[N_NODE];          // degree counts (zero invariant between calls)
__device__ int    g_rowptr[N_NODE + 1];
__device__ int    g_cur[N_NODE];          // fill cursors (re-init by scan each call)
__device__ int    g_scanval[64];          // chained-scan running totals
__device__ int    g_flag[64];             // chained-scan ready flags (reset by k_fill)
__device__ int2   g_epk[N_EDGE];          // packed (col, half2(v,v)) in CSR order
__device__ float  g_C[16];                // C[L][k] combination coefficients

// Pure degree histogram, 4 edges per thread (MLP=4)
__global__ void k_deg(const int* __restrict__ row) {
    int t = blockIdx.x * blockDim.x + threadIdx.x;
    if (t >= EQ4) return;
    int r0 = __ldg(&row[t]);
    int r1 = __ldg(&row[t + EQ4]);
    int r2 = __ldg(&row[t + 2 * EQ4]);
    int r3 = __ldg(&row[t + 3 * EQ4]);
    atomicAdd(&g_cnt[r0], 1);
    atomicAdd(&g_cnt[r1], 1);
    atomicAdd(&g_cnt[r2], 1);
    atomicAdd(&g_cnt[r3], 1);
}

// ---------------- chained scan + (extra block) coefficient collapse ----------------
__global__ void __launch_bounds__(SCAN_BS) k_scan(const float* __restrict__ alphas,
                                                  const float* __restrict__ w,
                                                  const float* __restrict__ aarr,
                                                  const float* __restrict__ barr) {
    int b = blockIdx.x;

    // ---- extra block: compute C[L][k] (one lane per m-term + shuffle reduce) ----
    if (b == NBLK_SCAN) {
        if (threadIdx.x >= 32) return;
        int m = threadIdx.x;
        const float l = -1.0f, r = 1.0f;
        float C[16];
#pragma unroll
        for (int k = 0; k < 16; k++) C[k] = 0.0f;

        if (m < M_TERMS) {
            float a = aarr[m], bb = barr[m], wm = w[m];
            float P[DEPTH + 1][DEPTH + 1];
            for (int L = 0; L <= DEPTH; L++)
                for (int k = 0; k <= DEPTH; k++) P[L][k] = 0.0f;
            P[0][0] = 1.0f;

            float coef1 = (a - bb) * 0.5f - (a + bb + 2.0f) * 0.5f * (l + r) / (r - l);
            float coef2 = (a + bb + 2.0f) / (r - l);
            float al0 = alphas[0 * M_TERMS + m];
            P[1][0] = al0 * coef1;
            P[1][1] = al0 * coef2;

            for (int L = 2; L <= DEPTH; L++) {
                float Lf = (float)L;
                float coef_l     = 2.0f * Lf * (Lf + a + bb) * (2.0f * Lf - 2.0f + a + bb);
                float coef_lm1_1 = (2.0f * Lf + a + bb - 1.0f) * (2.0f * Lf + a + bb) * (2.0f * Lf + a + bb - 2.0f);
                float coef_lm1_2 = (2.0f * Lf + a + bb - 1.0f) * (a * a - bb * bb);
                float coef_lm2   = 2.0f * (Lf - 1.0f + a) * (Lf - 1.0f + bb) * (2.0f * Lf + a + bb);
                float alL   = alphas[(L - 1) * M_TERMS + m];
                float alLm1 = alphas[(L - 2) * M_TERMS + m];
                float t1 = alL * (coef_lm1_1 / coef_l);
                float t2 = alL * (coef_lm1_2 / coef_l);
                float t3 = alL * alLm1 * (coef_lm2 / coef_l);
                float t1_2 = t1 * (2.0f / (r - l));
                float t2_2 = t1 * ((r + l) / (r - l)) + t2;
                for (int k = 0; k <= L; k++) {
                    float pm1 = (k > 0) ? P[L - 1][k - 1] : 0.0f;
                    P[L][k] = t1_2 * pm1 - t2_2 * P[L - 1][k] - t3 * P[L - 2][k];
                }
            }
            for (int L = 0; L <= DEPTH; L++)
                for (int k = 0; k <= L; k++) C[L * 4 + k] = wm * P[L][k];
        }
#pragma unroll
        for (int k = 0; k < 16; k++) {
            float v = C[k];
#pragma unroll
            for (int o = 16; o >= 1; o >>= 1)
                v += __shfl_xor_sync(0xFFFFFFFFu, v, o);
            if (threadIdx.x == 0) g_C[k] = v;
        }
        return;
    }

    // ---- chained scan blocks ----
    __shared__ int warp_sums[32];
    __shared__ int s_prefix;
    int i = b * SCAN_BS + threadIdx.x;
    int lane = threadIdx.x & 31, wid = threadIdx.x >> 5;
    int v = (i < N_NODE) ? g_cnt[i] : 0;

    int incl = v;
#pragma unroll
    for (int o = 1; o < 32; o <<= 1) {
        int t = __shfl_up_sync(0xFFFFFFFFu, incl, o);
        if (lane >= o) incl += t;
    }
    if (lane == 31) warp_sums[wid] = incl;
    __syncthreads();
    if (wid == 0) {
        int s = warp_sums[lane];
#pragma unroll
        for (int o = 1; o < 32; o <<= 1) {
            int t = __shfl_up_sync(0xFFFFFFFFu, s, o);
            if (lane >= o) s += t;
        }
        warp_sums[lane] = s;
    }
    __syncthreads();
    int block_excl = (wid > 0) ? warp_sums[wid - 1] : 0;
    int incl_block = incl + block_excl;
    int block_total = warp_sums[31];

    if (threadIdx.x == 0) {
        int prefix = 0;
        if (b > 0) {
            while (atomicAdd(&g_flag[b - 1], 0) == 0) { }
            __threadfence();
            prefix = g_scanval[b - 1];
        }
        g_scanval[b] = prefix + block_total;
        __threadfence();
        atomicExch(&g_flag[b], 1);
        s_prefix = prefix;
    }
    __syncthreads();

    if (i < N_NODE) {
        int excl = s_prefix + incl_block - v;
        g_rowptr[i] = excl;
        g_cur[i] = excl;                              // fill cursor
        float d = (v == 0) ? 1.0f : (float)v;
        g_dinv[i] = rsqrtf(d);
        g_cnt[i] = 0;                                 // restore zero invariant
    }
    if (i == 0) g_rowptr[N_NODE] = N_EDGE;
}

// Fill CSR (4 edges/thread) + x -> fp16 conversion fused.
// epk.y holds packed half2(v, v) for direct HFMA2 in the SpMM.
__global__ void k_fill_xtoh(const int* __restrict__ row, const int* __restrict__ col,
                            const float* __restrict__ ea, const float* __restrict__ x) {
    int t = blockIdx.x * blockDim.x + threadIdx.x;
    if (t < 64) g_flag[t] = 0;                        // reset scan flags for next call
    if (t >= EQ4) return;
    int r0 = __ldg(&row[t]);
    int r1 = __ldg(&row[t + EQ4]);
    int r2 = __ldg(&row[t + 2 * EQ4]);
    int r3 = __ldg(&row[t + 3 * EQ4]);
    int c0 = __ldg(&col[t]);
    int c1 = __ldg(&col[t + EQ4]);
    int c2 = __ldg(&col[t + 2 * EQ4]);
    int c3 = __ldg(&col[t + 3 * EQ4]);
    float e0 = __ldg(&ea[t]);
    float e1 = __ldg(&ea[t + EQ4]);
    float e2 = __ldg(&ea[t + 2 * EQ4]);
    float e3 = __ldg(&ea[t + 3 * EQ4]);
    // x -> fp16 (independent traffic; hides behind the random dinv reads/atomics)
    float4 v0 = __ldg((const float4*)(x + (size_t)t * 4));
    float4 v1 = __ldg((const float4*)(x + (size_t)(t + EQ4) * 4));
    float4 v2 = __ldg((const float4*)(x + (size_t)(t + 2 * EQ4) * 4));
    float4 v3 = __ldg((const float4*)(x + (size_t)(t + 3 * EQ4) * 4));
    float d0 = __ldg(&g_dinv[c0]);
    float d1 = __ldg(&g_dinv[c1]);
    float d2 = __ldg(&g_dinv[c2]);
    float d3 = __ldg(&g_dinv[c3]);
#define CVT_ST(vv, ee)                                                        \
    {                                                                         \
        __half2 h0 = __floats2half2_rn(vv.x, vv.y);                           \
        __half2 h1 = __floats2half2_rn(vv.z, vv.w);                           \
        *(uint2*)(g_xh + (size_t)(ee) * 4) =                                  \
            make_uint2(*(uint32_t*)&h0, *(uint32_t*)&h1);                     \
    }
    CVT_ST(v0, t); CVT_ST(v1, t + EQ4); CVT_ST(v2, t + 2 * EQ4); CVT_ST(v3, t + 3 * EQ4);
    int p0 = atomicAdd(&g_cur[r0], 1);
    int p1 = atomicAdd(&g_cur[r1], 1);
    int p2 = atomicAdd(&g_cur[r2], 1);
    int p3 = atomicAdd(&g_cur[r3], 1);
#define PACKV(vf)                                                             \
    ({ __half2 hv = __half2half2(__float2half_rn(vf)); *(int*)&hv; })
    g_epk[p0] = make_int2(c0, PACKV(e0 * d0));
    g_epk[p1] = make_int2(c1, PACKV(e1 * d1));
    g_epk[p2] = make_int2(c2, PACKV(e2 * d2));
    g_epk[p3] = make_int2(c3, PACKV(e3 * d3));
}

// ---------------- SpMM edge-group core: 4 edges, HFMA2 partials, fp32 flush ----------
#define EDGE_GROUP4(PTR, pk0, pk1, pk2, pk3)                                  \
    {                                                                         \
        uint4 r0 = __ldg((const uint4*)(PTR + (size_t)pk0.x * D_FEAT + c));   \
        uint4 r1 = __ldg((const uint4*)(PTR + (size_t)pk1.x * D_FEAT + c));   \
        uint4 r2 = __ldg((const uint4*)(PTR + (size_t)pk2.x * D_FEAT + c));   \
        uint4 r3 = __ldg((const uint4*)(PTR + (size_t)pk3.x * D_FEAT + c));   \
        __half2 w0 = *(__half2*)&pk0.y, w1 = *(__half2*)&pk1.y;               \
        __half2 w2 = *(__half2*)&pk2.y, w3 = *(__half2*)&pk3.y;               \
        __half2 h0 = __hmul2(w0, *(__half2*)&r0.x);                           \
        __half2 h1 = __hmul2(w0, *(__half2*)&r0.y);                           \
        __half2 h2 = __hmul2(w0, *(__half2*)&r0.z);                           \
        __half2 h3 = __hmul2(w0, *(__half2*)&r0.w);                           \
        h0 = __hfma2(w1, *(__half2*)&r1.x, h0);                               \
        h1 = __hfma2(w1, *(__half2*)&r1.y, h1);                               \
        h2 = __hfma2(w1, *(__half2*)&r1.z, h2);                               \
        h3 = __hfma2(w1, *(__half2*)&r1.w, h3);                               \
        h0 = __hfma2(w2, *(__half2*)&r2.x, h0);                               \
        h1 = __hfma2(w2, *(__half2*)&r2.y, h1);                               \
        h2 = __hfma2(w2, *(__half2*)&r2.z, h2);                               \
        h3 = __hfma2(w2, *(__half2*)&r2.w, h3);                               \
        h0 = __hfma2(w3, *(__half2*)&r3.x, h0);                               \
        h1 = __hfma2(w3, *(__half2*)&r3.y, h1);                               \
        h2 = __hfma2(w3, *(__half2*)&r3.z, h2);                               \
        h3 = __hfma2(w3, *(__half2*)&r3.w, h3);                               \
        float2 f0 = __half22float2(h0);                                       \
        float2 f1 = __half22float2(h1);                                       \
        float2 f2 = __half22float2(h2);                                       \
        float2 f3 = __half22float2(h3);                                       \
        a0 += f0.x; a1 += f0.y; a2 += f1.x; a3 += f1.y;                       \
        a4 += f2.x; a5 += f2.y; a6 += f3.x; a7 += f3.y;                       \
    }

#define EDGE_TAIL(PTR, pk)                                                    \
    {                                                                         \
        float vv = __half2float(((__half2*)&pk.y)->x);                        \
        uint4 rr = __ldg((const uint4*)(PTR + (size_t)pk.x * D_FEAT + c));    \
        float2 f0 = __half22float2(*(__half2*)&rr.x);                         \
        float2 f1 = __half22float2(*(__half2*)&rr.y);                         \
        float2 f2 = __half22float2(*(__half2*)&rr.z);                         \
        float2 f3 = __half22float2(*(__half2*)&rr.w);                         \
        a0 = fmaf(vv, f0.x, a0); a1 = fmaf(vv, f0.y, a1);                     \
        a2 = fmaf(vv, f1.x, a2); a3 = fmaf(vv, f1.y, a3);                     \
        a4 = fmaf(vv, f2.x, a4); a5 = fmaf(vv, f2.y, a5);                     \
        a6 = fmaf(vv, f3.x, a6); a7 = fmaf(vv, f3.y, a7);                     \
    }

// ---------------- CSR SpMM: 8 threads per node, 8 feats each ----------------
__global__ void __launch_bounds__(256) k_spmm(const __half* __restrict__ xin,
                                              __half* __restrict__ y16) {
    int t = blockIdx.x * blockDim.x + threadIdx.x;
    int n = t >> 3;
    if (n >= N_NODE) return;
    int c = (t & 7) << 3;
    int s = __ldg(&g_rowptr[n]);
    int e = __ldg(&g_rowptr[n + 1]);

    float a0 = 0.f, a1 = 0.f, a2 = 0.f, a3 = 0.f;
    float a4 = 0.f, a5 = 0.f, a6 = 0.f, a7 = 0.f;

    int i = s;
    for (; i + 4 <= e; i += 4) {
        int2 p0 = __ldg(&g_epk[i]);
        int2 p1 = __ldg(&g_epk[i + 1]);
        int2 p2 = __ldg(&g_epk[i + 2]);
        int2 p3 = __ldg(&g_epk[i + 3]);
        EDGE_GROUP4(xin, p0, p1, p2, p3);
    }
    for (; i < e; i++) {
        int2 pk = __ldg(&g_epk[i]);
        EDGE_TAIL(xin, pk);
    }

    float dn = __ldg(&g_dinv[n]);           // fold dinv[row] here (fp32)
    a0 *= dn; a1 *= dn; a2 *= dn; a3 *= dn;
    a4 *= dn; a5 *= dn; a6 *= dn; a7 *= dn;

    size_t off = (size_t)n * D_FEAT + c;
    __half2 o0 = __floats2half2_rn(a0, a1);
    __half2 o1 = __floats2half2_rn(a2, a3);
    __half2 o2 = __floats2half2_rn(a4, a5);
    __half2 o3 = __floats2half2_rn(a6, a7);
    *(uint4*)(y16 + off) = make_uint4(*(uint32_t*)&o0, *(uint32_t*)&o1,
                                      *(uint32_t*)&o2, *(uint32_t*)&o3);
}

// ---------------- fused SpMM3 + epilogue ----------------
__global__ void __launch_bounds__(256) k_spmm_out(const __half* __restrict__ y2h,
                                                  const float* __restrict__ x,
                                                  float* __restrict__ out) {
    int t = blockIdx.x * blockDim.x + threadIdx.x;
    int n = t >> 3;
    if (n >= N_NODE) return;
    int c = (t & 7) << 3;
    int s = __ldg(&g_rowptr[n]);
    int e = __ldg(&g_rowptr[n + 1]);

    float a0 = 0.f, a1 = 0.f, a2 = 0.f, a3 = 0.f;
    float a4 = 0.f, a5 = 0.f, a6 = 0.f, a7 = 0.f;

    int i = s;
    for (; i + 4 <= e; i += 4) {
        int2 p0 = __ldg(&g_epk[i]);
        int2 p1 = __ldg(&g_epk[i + 1]);
        int2 p2 = __ldg(&g_epk[i + 2]);
        int2 p3 = __ldg(&g_epk[i + 3]);
        EDGE_GROUP4(y2h, p0, p1, p2, p3);
    }
    for (; i < e; i++) {
        int2 pk = __ldg(&g_epk[i]);
        EDGE_TAIL(y2h, pk);
    }

    float dn = __ldg(&g_dinv[n]);
    a0 *= dn; a1 *= dn; a2 *= dn; a3 *= dn;
    a4 *= dn; a5 *= dn; a6 *= dn; a7 *= dn;

    size_t off = (size_t)n * D_FEAT + c;
    float4 x0 = __ldg((const float4*)(x + off));
    float4 x1 = __ldg((const float4*)(x + off + 4));

    uint4 y1r = *(const uint4*)(g_yh + off);
    uint4 y2r = *(const uint4*)(g_yh + (size_t)NF + off);
    float2 p00 = __half22float2(*(__half2*)&y1r.x);
    float2 p01 = __half22float2(*(__half2*)&y1r.y);
    float2 p02 = __half22float2(*(__half2*)&y1r.z);
    float2 p03 = __half22float2(*(__half2*)&y1r.w);
    float2 q00 = __half22float2(*(__half2*)&y2r.x);
    float2 q01 = __half22float2(*(__half2*)&y2r.y);
    float2 q02 = __half22float2(*(__half2*)&y2r.z);
    float2 q03 = __half22float2(*(__half2*)&y2r.w);

    float* ob = out + (size_t)n * ((DEPTH + 1) * D_FEAT) + c;
#pragma unroll
    for (int L = 0; L <= DEPTH; L++) {
        float c0 = g_C[L * 4 + 0], c1 = g_C[L * 4 + 1];
        float c2 = g_C[L * 4 + 2], c3 = g_C[L * 4 + 3];
        float4 o;
        o.x = c0 * x0.x + c1 * p00.x + c2 * q00.x + c3 * a0;
        o.y = c0 * x0.y + c1 * p00.y + c2 * q00.y + c3 * a1;
        o.z = c0 * x0.z + c1 * p01.x + c2 * q01.x + c3 * a2;
        o.w = c0 * x0.w + c1 * p01.y + c2 * q01.y + c3 * a3;
        *(float4*)(ob + (size_t)L * D_FEAT) = o;
        float4 u;
        u.x = c0 * x1.x + c1 * p02.x + c2 * q02.x + c3 * a4;
        u.y = c0 * x1.y + c1 * p02.y + c2 * q02.y + c3 * a5;
        u.z = c0 * x1.z + c1 * p03.x + c2 * q03.x + c3 * a6;
        u.w = c0 * x1.w + c1 * p03.y + c2 * q03.y + c3 * a7;
        *(float4*)(ob + (size_t)L * D_FEAT + 4) = u;
    }
}

// ---------------- launch ----------------
extern "C" void kernel_launch(void* const* d_in, const int* in_sizes, int n_in,
                              void* d_out, int out_size) {
    const float* x      = (const float*)d_in[0];
    const int*   eidx   = (const int*)d_in[1];      // (2, N_EDGE): row then col
    const float* eattr  = (const float*)d_in[2];
    const float* alphas = (const float*)d_in[3];
    const float* w      = (const float*)d_in[4];
    const float* a_arr  = (const float*)d_in[5];
    const float* b_arr  = (const float*)d_in[6];
    float* out = (float*)d_out;

    const int* row = eidx;
    const int* col = eidx + N_EDGE;

    static __half* yh = nullptr;
    static __half* xh = nullptr;
    if (!yh) {
        cudaGetSymbolAddress((void**)&yh, g_yh);
        cudaGetSymbolAddress((void**)&xh, g_xh);
    }

    const int B = 256;
    // launch index 3 == k_spmm #1  (profiler captures index 3)
    k_deg<<<(EQ4 + B - 1) / B, B>>>(row);                            // 0
    k_scan<<<NBLK_SCAN + 1, SCAN_BS>>>(alphas, w, a_arr, b_arr);     // 1 (+coef block)
    k_fill_xtoh<<<(EQ4 + B - 1) / B, B>>>(row, col, eattr, x);       // 2

    const int spmm_blocks = (N_NODE * 8 + B - 1) / B;   // 1563
    k_spmm<<<spmm_blocks, B>>>(xh, yh);                              // 3  <-- profiled
    k_spmm<<<spmm_blocks, B>>>(yh, yh + NF);                         // 4
    k_spmm_out<<<spmm_blocks, B>>>(yh + NF, x, out);                 // 5
}

// round 14
// speedup vs baseline: 1.0030x; 1.0030x over previous
#include <cuda_runtime.h>
#include <cuda_fp16.h>
#include <cstdint>

#define N_NODE 50000
#define N_EDGE 800000
#define D_FEAT 64
#define DEPTH  3
#define M_TERMS 11
#define NF (N_NODE * D_FEAT)   // 3,200,000
#define SCAN_BS 1024
#define NBLK_SCAN ((N_NODE + SCAN_BS - 1) / SCAN_BS)   // 49
#define EQ4 (N_EDGE / 4)       // 200,000

// ---------------- scratch (device globals; zero-initialized at load) ----------------
__device__ __half g_yh[2 * NF];           // S^1 x, S^2 x (fp16: gather + epilogue source)
__device__ __half g_xh[NF];               // fp16 copy of x
__device__ float  g_dinv[N_NODE];
__device__ int    g_cnt[N_NODE];          // degree counts (zero invariant between calls)
__device__ int    g_rowptr[N_NODE + 1];
__device__ int    g_rank[N_EDGE];         // within-row rank of each edge (from deg pass)
__device__ int    g_scanval[64];          // chained-scan running totals
__device__ int    g_flag[64];             // chained-scan ready flags (reset by k_fill)
__device__ int2   g_epk[N_EDGE];          // packed (col, half2(v,v)) in CSR order
__device__ float  g_C[16];                // C[L][k] combination coefficients

// Degree histogram + per-edge rank capture + x -> fp16, 4 items per thread
__global__ void k_deg_xtoh(const int* __restrict__ row, const float* __restrict__ x) {
    int t = blockIdx.x * blockDim.x + threadIdx.x;
    if (t >= EQ4) return;
    int r0 = __ldg(&row[t]);
    int r1 = __ldg(&row[t + EQ4]);
    int r2 = __ldg(&row[t + 2 * EQ4]);
    int r3 = __ldg(&row[t + 3 * EQ4]);
    float4 v0 = __ldg((const float4*)(x + (size_t)t * 4));
    float4 v1 = __ldg((const float4*)(x + (size_t)(t + EQ4) * 4));
    float4 v2 = __ldg((const float4*)(x + (size_t)(t + 2 * EQ4) * 4));
    float4 v3 = __ldg((const float4*)(x + (size_t)(t + 3 * EQ4) * 4));
    int k0 = atomicAdd(&g_cnt[r0], 1);
    int k1 = atomicAdd(&g_cnt[r1], 1);
    int k2 = atomicAdd(&g_cnt[r2], 1);
    int k3 = atomicAdd(&g_cnt[r3], 1);
    g_rank[t]           = k0;
    g_rank[t + EQ4]     = k1;
    g_rank[t + 2 * EQ4] = k2;
    g_rank[t + 3 * EQ4] = k3;
#define CVT_ST(vv, ee)                                                        \
    {                                                                         \
        __half2 h0 = __floats2half2_rn(vv.x, vv.y);                           \
        __half2 h1 = __floats2half2_rn(vv.z, vv.w);                           \
        *(uint2*)(g_xh + (size_t)(ee) * 4) =                                  \
            make_uint2(*(uint32_t*)&h0, *(uint32_t*)&h1);                     \
    }
    CVT_ST(v0, t); CVT_ST(v1, t + EQ4); CVT_ST(v2, t + 2 * EQ4); CVT_ST(v3, t + 3 * EQ4);
}

// ---------------- chained scan + (extra block) coefficient collapse ----------------
__global__ void __launch_bounds__(SCAN_BS) k_scan(const float* __restrict__ alphas,
                                                  const float* __restrict__ w,
                                                  const float* __restrict__ aarr,
                                                  const float* __restrict__ barr) {
    int b = blockIdx.x;

    if (b == NBLK_SCAN) {   // ---- coefficient block ----
        if (threadIdx.x >= 32) return;
        int m = threadIdx.x;
        const float l = -1.0f, r = 1.0f;
        float C[16];
#pragma unroll
        for (int k = 0; k < 16; k++) C[k] = 0.0f;

        if (m < M_TERMS) {
            float a = aarr[m], bb = barr[m], wm = w[m];
            float P[DEPTH + 1][DEPTH + 1];
            for (int L = 0; L <= DEPTH; L++)
                for (int k = 0; k <= DEPTH; k++) P[L][k] = 0.0f;
            P[0][0] = 1.0f;

            float coef1 = (a - bb) * 0.5f - (a + bb + 2.0f) * 0.5f * (l + r) / (r - l);
            float coef2 = (a + bb + 2.0f) / (r - l);
            float al0 = alphas[0 * M_TERMS + m];
            P[1][0] = al0 * coef1;
            P[1][1] = al0 * coef2;

            for (int L = 2; L <= DEPTH; L++) {
                float Lf = (float)L;
                float coef_l     = 2.0f * Lf * (Lf + a + bb) * (2.0f * Lf - 2.0f + a + bb);
                float coef_lm1_1 = (2.0f * Lf + a + bb - 1.0f) * (2.0f * Lf + a + bb) * (2.0f * Lf + a + bb - 2.0f);
                float coef_lm1_2 = (2.0f * Lf + a + bb - 1.0f) * (a * a - bb * bb);
                float coef_lm2   = 2.0f * (Lf - 1.0f + a) * (Lf - 1.0f + bb) * (2.0f * Lf + a + bb);
                float alL   = alphas[(L - 1) * M_TERMS + m];
                float alLm1 = alphas[(L - 2) * M_TERMS + m];
                float t1 = alL * (coef_lm1_1 / coef_l);
                float t2 = alL * (coef_lm1_2 / coef_l);
                float t3 = alL * alLm1 * (coef_lm2 / coef_l);
                float t1_2 = t1 * (2.0f / (r - l));
                float t2_2 = t1 * ((r + l) / (r - l)) + t2;
                for (int k = 0; k <= L; k++) {
                    float pm1 = (k > 0) ? P[L - 1][k - 1] : 0.0f;
                    P[L][k] = t1_2 * pm1 - t2_2 * P[L - 1][k] - t3 * P[L - 2][k];
                }
            }
            for (int L = 0; L <= DEPTH; L++)
                for (int k = 0; k <= L; k++) C[L * 4 + k] = wm * P[L][k];
        }
#pragma unroll
        for (int k = 0; k < 16; k++) {
            float v = C[k];
#pragma unroll
            for (int o = 16; o >= 1; o >>= 1)
                v += __shfl_xor_sync(0xFFFFFFFFu, v, o);
            if (threadIdx.x == 0) g_C[k] = v;
        }
        return;
    }

    // ---- chained scan blocks ----
    __shared__ int warp_sums[32];
    __shared__ int s_prefix;
    int i = b * SCAN_BS + threadIdx.x;
    int lane = threadIdx.x & 31, wid = threadIdx.x >> 5;
    int v = (i < N_NODE) ? g_cnt[i] : 0;

    int incl = v;
#pragma unroll
    for (int o = 1; o < 32; o <<= 1) {
        int t = __shfl_up_sync(0xFFFFFFFFu, incl, o);
        if (lane >= o) incl += t;
    }
    if (lane == 31) warp_sums[wid] = incl;
    __syncthreads();
    if (wid == 0) {
        int s = warp_sums[lane];
#pragma unroll
        for (int o = 1; o < 32; o <<= 1) {
            int t = __shfl_up_sync(0xFFFFFFFFu, s, o);
            if (lane >= o) s += t;
        }
        warp_sums[lane] = s;
    }
    __syncthreads();
    int block_excl = (wid > 0) ? warp_sums[wid - 1] : 0;
    int incl_block = incl + block_excl;
    int block_total = warp_sums[31];

    if (threadIdx.x == 0) {
        int prefix = 0;
        if (b > 0) {
            while (atomicAdd(&g_flag[b - 1], 0) == 0) { }
            __threadfence();
            prefix = g_scanval[b - 1];
        }
        g_scanval[b] = prefix + block_total;
        __threadfence();
        atomicExch(&g_flag[b], 1);
        s_prefix = prefix;
    }
    __syncthreads();

    if (i < N_NODE) {
        int excl = s_prefix + incl_block - v;
        g_rowptr[i] = excl;
        float d = (v == 0) ? 1.0f : (float)v;
        g_dinv[i] = rsqrtf(d);
        g_cnt[i] = 0;                                 // restore zero invariant
    }
    if (i == 0) g_rowptr[N_NODE] = N_EDGE;
}

// Fill CSR (4 edges/thread), NO atomics: pos = rowptr[row] + rank (from deg pass).
__global__ void k_fill(const int* __restrict__ row, const int* __restrict__ col,
                       const float* __restrict__ ea) {
    int t = blockIdx.x * blockDim.x + threadIdx.x;
    if (t < 64) g_flag[t] = 0;                        // reset scan flags for next call
    if (t >= EQ4) return;
    int r0 = __ldg(&row[t]);
    int r1 = __ldg(&row[t + EQ4]);
    int r2 = __ldg(&row[t + 2 * EQ4]);
    int r3 = __ldg(&row[t + 3 * EQ4]);
    int c0 = __ldg(&col[t]);
    int c1 = __ldg(&col[t + EQ4]);
    int c2 = __ldg(&col[t + 2 * EQ4]);
    int c3 = __ldg(&col[t + 3 * EQ4]);
    float e0 = __ldg(&ea[t]);
    float e1 = __ldg(&ea[t + EQ4]);
    float e2 = __ldg(&ea[t + 2 * EQ4]);
    float e3 = __ldg(&ea[t + 3 * EQ4]);
    int k0 = __ldg(&g_rank[t]);
    int k1 = __ldg(&g_rank[t + EQ4]);
    int k2 = __ldg(&g_rank[t + 2 * EQ4]);
    int k3 = __ldg(&g_rank[t + 3 * EQ4]);
    float d0 = __ldg(&g_dinv[c0]);
    float d1 = __ldg(&g_dinv[c1]);
    float d2 = __ldg(&g_dinv[c2]);
    float d3 = __ldg(&g_dinv[c3]);
    int p0 = __ldg(&g_rowptr[r0]) + k0;
    int p1 = __ldg(&g_rowptr[r1]) + k1;
    int p2 = __ldg(&g_rowptr[r2]) + k2;
    int p3 = __ldg(&g_rowptr[r3]) + k3;
#define PACKV(vf)                                                             \
    ({ __half2 hv = __half2half2(__float2half_rn(vf)); *(int*)&hv; })
    g_epk[p0] = make_int2(c0, PACKV(e0 * d0));
    g_epk[p1] = make_int2(c1, PACKV(e1 * d1));
    g_epk[p2] = make_int2(c2, PACKV(e2 * d2));
    g_epk[p3] = make_int2(c3, PACKV(e3 * d3));
}

// ---------------- SpMM edge-group core: 4 edges, HFMA2 into fp16 partials ----------
#define EDGE_MAC4(PTR, pk0, pk1, pk2, pk3)                                    \
    {                                                                         \
        uint4 r0 = __ldg((const uint4*)(PTR + (size_t)pk0.x * D_FEAT + c));   \
        uint4 r1 = __ldg((const uint4*)(PTR + (size_t)pk1.x * D_FEAT + c));   \
        uint4 r2 = __ldg((const uint4*)(PTR + (size_t)pk2.x * D_FEAT + c));   \
        uint4 r3 = __ldg((const uint4*)(PTR + (size_t)pk3.x * D_FEAT + c));   \
        __half2 w0 = *(__half2*)&pk0.y, w1 = *(__half2*)&pk1.y;               \
        __half2 w2 = *(__half2*)&pk2.y, w3 = *(__half2*)&pk3.y;               \
        h0 = __hfma2(w0, *(__half2*)&r0.x, h0);                               \
        h1 = __hfma2(w0, *(__half2*)&r0.y, h1);                               \
        h2 = __hfma2(w0, *(__half2*)&r0.z, h2);                               \
        h3 = __hfma2(w0, *(__half2*)&r0.w, h3);                               \
        h0 = __hfma2(w1, *(__half2*)&r1.x, h0);                               \
        h1 = __hfma2(w1, *(__half2*)&r1.y, h1);                               \
        h2 = __hfma2(w1, *(__half2*)&r1.z, h2);                               \
        h3 = __hfma2(w1, *(__half2*)&r1.w, h3);                               \
        h0 = __hfma2(w2, *(__half2*)&r2.x, h0);                               \
        h1 = __hfma2(w2, *(__half2*)&r2.y, h1);                               \
        h2 = __hfma2(w2, *(__half2*)&r2.z, h2);                               \
        h3 = __hfma2(w2, *(__half2*)&r2.w, h3);                               \
        h0 = __hfma2(w3, *(__half2*)&r3.x, h0);                               \
        h1 = __hfma2(w3, *(__half2*)&r3.y, h1);                               \
        h2 = __hfma2(w3, *(__half2*)&r3.z, h2);                               \
        h3 = __hfma2(w3, *(__half2*)&r3.w, h3);                               \
    }

#define FLUSH_H()                                                             \
    {                                                                         \
        float2 f0 = __half22float2(h0);                                       \
        float2 f1 = __half22float2(h1);                                       \
        float2 f2 = __half22float2(h2);                                       \
        float2 f3 = __half22float2(h3);                                       \
        a0 += f0.x; a1 += f0.y; a2 += f1.x; a3 += f1.y;                       \
        a4 += f2.x; a5 += f2.y; a6 += f3.x; a7 += f3.y;                       \
        h0 = h1 = h2 = h3 = __half2half2(__float2half_rn(0.0f));              \
    }

#define EDGE_TAIL(PTR, pk)                                                    \
    {                                                                         \
        float vv = __half2float(((__half2*)&pk.y)->x);                        \
        uint4 rr = __ldg((const uint4*)(PTR + (size_t)pk.x * D_FEAT + c));    \
        float2 f0 = __half22float2(*(__half2*)&rr.x);                         \
        float2 f1 = __half22float2(*(__half2*)&rr.y);                         \
        float2 f2 = __half22float2(*(__half2*)&rr.z);                         \
        float2 f3 = __half22float2(*(__half2*)&rr.w);                         \
        a0 = fmaf(vv, f0.x, a0); a1 = fmaf(vv, f0.y, a1);                     \
        a2 = fmaf(vv, f1.x, a2); a3 = fmaf(vv, f1.y, a3);                     \
        a4 = fmaf(vv, f2.x, a4); a5 = fmaf(vv, f2.y, a5);                     \
        a6 = fmaf(vv, f3.x, a6); a7 = fmaf(vv, f3.y, a7);                     \
    }

// Shared gather body: 8 edges in flight (all 8 epk + 8 row loads issued up front)
#define SPMM_BODY(PTR)                                                        \
    float a0 = 0.f, a1 = 0.f, a2 = 0.f, a3 = 0.f;                             \
    float a4 = 0.f, a5 = 0.f, a6 = 0.f, a7 = 0.f;                             \
    __half2 h0, h1, h2, h3;                                                   \
    h0 = h1 = h2 = h3 = __half2half2(__float2half_rn(0.0f));                  \
    int i = s;                                                                \
    for (; i + 8 <= e; i += 8) {                                              \
        int2 p0 = __ldg(&g_epk[i]);                                           \
        int2 p1 = __ldg(&g_epk[i + 1]);                                       \
        int2 p2 = __ldg(&g_epk[i + 2]);                                       \
        int2 p3 = __ldg(&g_epk[i + 3]);                                       \
        int2 p4 = __ldg(&g_epk[i + 4]);                                       \
        int2 p5 = __ldg(&g_epk[i + 5]);                                       \
        int2 p6 = __ldg(&g_epk[i + 6]);                                       \
        int2 p7 = __ldg(&g_epk[i + 7]);                                       \
        EDGE_MAC4(PTR, p0, p1, p2, p3);                                       \
        EDGE_MAC4(PTR, p4, p5, p6, p7);                                       \
        FLUSH_H();                                                            \
    }                                                                         \
    for (; i + 4 <= e; i += 4) {                                              \
        int2 p0 = __ldg(&g_epk[i]);                                           \
        int2 p1 = __ldg(&g_epk[i + 1]);                                       \
        int2 p2 = __ldg(&g_epk[i + 2]);                                       \
        int2 p3 = __ldg(&g_epk[i + 3]);                                       \
        EDGE_MAC4(PTR, p0, p1, p2, p3);                                       \
        FLUSH_H();                                                            \
    }                                                                         \
    for (; i < e; i++) {                                                      \
        int2 pk = __ldg(&g_epk[i]);                                           \
        EDGE_TAIL(PTR, pk);                                                   \
    }                                                                         \
    float dn = __ldg(&g_dinv[n]);                                             \
    a0 *= dn; a1 *= dn; a2 *= dn; a3 *= dn;                                   \
    a4 *= dn; a5 *= dn; a6 *= dn; a7 *= dn;

// ---------------- CSR SpMM: 8 threads per node, 8 feats each ----------------
__global__ void __launch_bounds__(256) k_spmm(const __half* __restrict__ xin,
                                              __half* __restrict__ y16) {
    int t = blockIdx.x * blockDim.x + threadIdx.x;
    int n = t >> 3;
    if (n >= N_NODE) return;
    int c = (t & 7) << 3;
    int s = __ldg(&g_rowptr[n]);
    int e = __ldg(&g_rowptr[n + 1]);

    SPMM_BODY(xin);

    size_t off = (size_t)n * D_FEAT + c;
    __half2 o0 = __floats2half2_rn(a0, a1);
    __half2 o1 = __floats2half2_rn(a2, a3);
    __half2 o2 = __floats2half2_rn(a4, a5);
    __half2 o3 = __floats2half2_rn(a6, a7);
    *(uint4*)(y16 + off) = make_uint4(*(uint32_t*)&o0, *(uint32_t*)&o1,
                                      *(uint32_t*)&o2, *(uint32_t*)&o3);
}

// ---------------- fused SpMM3 + epilogue ----------------
__global__ void __launch_bounds__(256) k_spmm_out(const __half* __restrict__ y2h,
                                                  const float* __restrict__ x,
                                                  float* __restrict__ out) {
    int t = blockIdx.x * blockDim.x + threadIdx.x;
    int n = t >> 3;
    if (n >= N_NODE) return;
    int c = (t & 7) << 3;
    int s = __ldg(&g_rowptr[n]);
    int e = __ldg(&g_rowptr[n + 1]);

    SPMM_BODY(y2h);

    size_t off = (size_t)n * D_FEAT + c;
    float4 x0 = __ldg((const float4*)(x + off));
    float4 x1 = __ldg((const float4*)(x + off + 4));

    uint4 y1r = *(const uint4*)(g_yh + off);
    uint4 y2r = *(const uint4*)(g_yh + (size_t)NF + off);
    float2 p00 = __half22float2(*(__half2*)&y1r.x);
    float2 p01 = __half22float2(*(__half2*)&y1r.y);
    float2 p02 = __half22float2(*(__half2*)&y1r.z);
    float2 p03 = __half22float2(*(__half2*)&y1r.w);
    float2 q00 = __half22float2(*(__half2*)&y2r.x);
    float2 q01 = __half22float2(*(__half2*)&y2r.y);
    float2 q02 = __half22float2(*(__half2*)&y2r.z);
    float2 q03 = __half22float2(*(__half2*)&y2r.w);

    float* ob = out + (size_t)n * ((DEPTH + 1) * D_FEAT) + c;
#pragma unroll
    for (int L = 0; L <= DEPTH; L++) {
        float c0 = g_C[L * 4 + 0], c1 = g_C[L * 4 + 1];
        float c2 = g_C[L * 4 + 2], c3 = g_C[L * 4 + 3];
        float4 o;
        o.x = c0 * x0.x + c1 * p00.x + c2 * q00.x + c3 * a0;
        o.y = c0 * x0.y + c1 * p00.y + c2 * q00.y + c3 * a1;
        o.z = c0 * x0.z + c1 * p01.x + c2 * q01.x + c3 * a2;
        o.w = c0 * x0.w + c1 * p01.y + c2 * q01.y + c3 * a3;
        *(float4*)(ob + (size_t)L * D_FEAT) = o;
        float4 u;
        u.x = c0 * x1.x + c1 * p02.x + c2 * q02.x + c3 * a4;
        u.y = c0 * x1.y + c1 * p02.y + c2 * q02.y + c3 * a5;
        u.z = c0 * x1.z + c1 * p03.x + c2 * q03.x + c3 * a6;
        u.w = c0 * x1.w + c1 * p03.y + c2 * q03.y + c3 * a7;
        *(float4*)(ob + (size_t)L * D_FEAT + 4) = u;
    }
}

// ---------------- launch ----------------
extern "C" void kernel_launch(void* const* d_in, const int* in_sizes, int n_in,
                              void* d_out, int out_size) {
    const float* x      = (const float*)d_in[0];
    const int*   eidx   = (const int*)d_in[1];      // (2, N_EDGE): row then col
    const float* eattr  = (const float*)d_in[2];
    const float* alphas = (const float*)d_in[3];
    const float* w      = (const float*)d_in[4];
    const float* a_arr  = (const float*)d_in[5];
    const float* b_arr  = (const float*)d_in[6];
    float* out = (float*)d_out;

    const int* row = eidx;
    const int* col = eidx + N_EDGE;

    static __half* yh = nullptr;
    static __half* xh = nullptr;
    if (!yh) {
        cudaGetSymbolAddress((void**)&yh, g_yh);
        cudaGetSymbolAddress((void**)&xh, g_xh);
    }

    const int B = 256;
    // launch index 3 == k_spmm #1  (profiler captures index 3)
    k_deg_xtoh<<<(EQ4 + B - 1) / B, B>>>(row, x);                    // 0
    k_scan<<<NBLK_SCAN + 1, SCAN_BS>>>(alphas, w, a_arr, b_arr);     // 1 (+coef block)
    k_fill<<<(EQ4 + B - 1) / B, B>>>(row, col, eattr);               // 2

    const int spmm_blocks = (N_NODE * 8 + B - 1) / B;   // 1563
    k_spmm<<<spmm_blocks, B>>>(xh, yh);                              // 3  <-- profiled
    k_spmm<<<spmm_blocks, B>>>(yh, yh + NF);                         // 4
    k_spmm_out<<<spmm_blocks, B>>>(yh + NF, x, out);                 // 5
}

// round 15
// speedup vs baseline: 1.5088x; 1.5042x over previous
#include <cuda_runtime.h>
#include <cuda_fp16.h>
#include <cstdint>

#define N_NODE 50000
#define N_EDGE 800000
#define D_FEAT 64
#define DEPTH  3
#define M_TERMS 11
#define NF (N_NODE * D_FEAT)      // 3,200,000
#define EQ4 (N_EDGE / 4)          // 200,000
#define NBLK 782
#define NTHR 256
#define TOT_THR (NBLK * NTHR)     // 200,192
#define SCAN_BLKS 196             // ceil(50000/256)
#define SPMM_SLOTS (N_NODE * 8)   // 400,000

// ---------------- scratch (device globals; zero-initialized at load) ----------------
__device__ __half g_yh[2 * NF];           // S^1 x, S^2 x (fp16)
__device__ __half g_xh[NF];               // fp16 copy of x
__device__ float  g_dinv[N_NODE];
__device__ int    g_cnt[N_NODE];          // degree counts (zero invariant between calls)
__device__ int    g_rowptr[N_NODE + 1];
__device__ int    g_rank[N_EDGE];         // within-row rank per edge
__device__ int    g_part[SCAN_BLKS];      // per-block scan partials
__device__ int2   g_epk[N_EDGE];          // (col, half2(v,v)) in CSR order
__device__ float  g_C[16];                // C[L][k]
__device__ volatile unsigned g_ctr[8];    // grid-barrier counters (0 at entry/exit)
__device__ volatile unsigned g_done;

// ---------------- software grid barrier (all NBLK blocks resident) ----------------
__device__ __forceinline__ void gbar(int idx) {
    __syncthreads();
    if (threadIdx.x == 0) {
        __threadfence();
        atomicAdd((unsigned*)&g_ctr[idx], 1u);
        while (g_ctr[idx] < (unsigned)NBLK) __nanosleep(64);
        __threadfence();
    }
    __syncthreads();
}

// ---------------- SpMM inner macros (R13 4-deep HFMA2 body — best measured) -------
#define EDGE_MAC4(PTR, pk0, pk1, pk2, pk3)                                    \
    {                                                                         \
        uint4 r0 = __ldg((const uint4*)(PTR + (size_t)pk0.x * D_FEAT + c));   \
        uint4 r1 = __ldg((const uint4*)(PTR + (size_t)pk1.x * D_FEAT + c));   \
        uint4 r2 = __ldg((const uint4*)(PTR + (size_t)pk2.x * D_FEAT + c));   \
        uint4 r3 = __ldg((const uint4*)(PTR + (size_t)pk3.x * D_FEAT + c));   \
        __half2 w0 = *(__half2*)&pk0.y, w1 = *(__half2*)&pk1.y;               \
        __half2 w2 = *(__half2*)&pk2.y, w3 = *(__half2*)&pk3.y;               \
        __half2 h0 = __hmul2(w0, *(__half2*)&r0.x);                           \
        __half2 h1 = __hmul2(w0, *(__half2*)&r0.y);                           \
        __half2 h2 = __hmul2(w0, *(__half2*)&r0.z);                           \
        __half2 h3 = __hmul2(w0, *(__half2*)&r0.w);                           \
        h0 = __hfma2(w1, *(__half2*)&r1.x, h0);                               \
        h1 = __hfma2(w1, *(__half2*)&r1.y, h1);                               \
        h2 = __hfma2(w1, *(__half2*)&r1.z, h2);                               \
        h3 = __hfma2(w1, *(__half2*)&r1.w, h3);                               \
        h0 = __hfma2(w2, *(__half2*)&r2.x, h0);                               \
        h1 = __hfma2(w2, *(__half2*)&r2.y, h1);                               \
        h2 = __hfma2(w2, *(__half2*)&r2.z, h2);                               \
        h3 = __hfma2(w2, *(__half2*)&r2.w, h3);                               \
        h0 = __hfma2(w3, *(__half2*)&r3.x, h0);                               \
        h1 = __hfma2(w3, *(__half2*)&r3.y, h1);                               \
        h2 = __hfma2(w3, *(__half2*)&r3.z, h2);                               \
        h3 = __hfma2(w3, *(__half2*)&r3.w, h3);                               \
        float2 f0 = __half22float2(h0);                                       \
        float2 f1 = __half22float2(h1);                                       \
        float2 f2 = __half22float2(h2);                                       \
        float2 f3 = __half22float2(h3);                                       \
        a0 += f0.x; a1 += f0.y; a2 += f1.x; a3 += f1.y;                       \
        a4 += f2.x; a5 += f2.y; a6 += f3.x; a7 += f3.y;                       \
    }

#define EDGE_TAIL(PTR, pk)                                                    \
    {                                                                         \
        float vv = __half2float(((__half2*)&pk.y)->x);                        \
        uint4 rr = __ldg((const uint4*)(PTR + (size_t)pk.x * D_FEAT + c));    \
        float2 f0 = __half22float2(*(__half2*)&rr.x);                         \
        float2 f1 = __half22float2(*(__half2*)&rr.y);                         \
        float2 f2 = __half22float2(*(__half2*)&rr.z);                         \
        float2 f3 = __half22float2(*(__half2*)&rr.w);                         \
        a0 = fmaf(vv, f0.x, a0); a1 = fmaf(vv, f0.y, a1);                     \
        a2 = fmaf(vv, f1.x, a2); a3 = fmaf(vv, f1.y, a3);                     \
        a4 = fmaf(vv, f2.x, a4); a5 = fmaf(vv, f2.y, a5);                     \
        a6 = fmaf(vv, f3.x, a6); a7 = fmaf(vv, f3.y, a7);                     \
    }

#define SPMM_GATHER(PTR)                                                      \
    float a0 = 0.f, a1 = 0.f, a2 = 0.f, a3 = 0.f;                             \
    float a4 = 0.f, a5 = 0.f, a6 = 0.f, a7 = 0.f;                             \
    int i = st;                                                               \
    for (; i + 4 <= en; i += 4) {                                             \
        int2 p0 = __ldg(&g_epk[i]);                                           \
        int2 p1 = __ldg(&g_epk[i + 1]);                                       \
        int2 p2 = __ldg(&g_epk[i + 2]);                                       \
        int2 p3 = __ldg(&g_epk[i + 3]);                                       \
        EDGE_MAC4(PTR, p0, p1, p2, p3);                                       \
    }                                                                         \
    for (; i < en; i++) {                                                     \
        int2 pk = __ldg(&g_epk[i]);                                           \
        EDGE_TAIL(PTR, pk);                                                   \
    }                                                                         \
    float dn = __ldg(&g_dinv[n]);                                             \
    a0 *= dn; a1 *= dn; a2 *= dn; a3 *= dn;                                   \
    a4 *= dn; a5 *= dn; a6 *= dn; a7 *= dn;

// ---------------- the one persistent kernel ----------------
__global__ void __launch_bounds__(NTHR, 6) k_all(
    const int* __restrict__ row, const int* __restrict__ col,
    const float* __restrict__ ea, const float* __restrict__ x,
    const float* __restrict__ alphas, const float* __restrict__ w,
    const float* __restrict__ aarr, const float* __restrict__ barr,
    float* __restrict__ out)
{
    __shared__ int wsum[8];
    int gtid = blockIdx.x * NTHR + threadIdx.x;

    // ======== P0: degree histogram + rank + x->fp16 ; spare warp: coefficients ====
    if (gtid < EQ4) {
        int t = gtid;
        int r0 = __ldg(&row[t]);
        int r1 = __ldg(&row[t + EQ4]);
        int r2 = __ldg(&row[t + 2 * EQ4]);
        int r3 = __ldg(&row[t + 3 * EQ4]);
        float4 v0 = __ldg((const float4*)(x + (size_t)t * 4));
        float4 v1 = __ldg((const float4*)(x + (size_t)(t + EQ4) * 4));
        float4 v2 = __ldg((const float4*)(x + (size_t)(t + 2 * EQ4) * 4));
        float4 v3 = __ldg((const float4*)(x + (size_t)(t + 3 * EQ4) * 4));
        int k0 = atomicAdd(&g_cnt[r0], 1);
        int k1 = atomicAdd(&g_cnt[r1], 1);
        int k2 = atomicAdd(&g_cnt[r2], 1);
        int k3 = atomicAdd(&g_cnt[r3], 1);
        g_rank[t]           = k0;
        g_rank[t + EQ4]     = k1;
        g_rank[t + 2 * EQ4] = k2;
        g_rank[t + 3 * EQ4] = k3;
#define CVT_ST(vv, ee)                                                        \
        {                                                                     \
            __half2 ha = __floats2half2_rn(vv.x, vv.y);                       \
            __half2 hb = __floats2half2_rn(vv.z, vv.w);                       \
            *(uint2*)(g_xh + (size_t)(ee) * 4) =                              \
                make_uint2(*(uint32_t*)&ha, *(uint32_t*)&hb);                 \
        }
        CVT_ST(v0, t); CVT_ST(v1, t + EQ4);
        CVT_ST(v2, t + 2 * EQ4); CVT_ST(v3, t + 3 * EQ4);
    } else if (blockIdx.x == NBLK - 1 && threadIdx.x >= 64 && threadIdx.x < 96) {
        // idle warp (gtid >= 200000): compute C[L][k], one m-term per lane
        int m = threadIdx.x - 64;
        const float l = -1.0f, r = 1.0f;
        float C[16];
#pragma unroll
        for (int k = 0; k < 16; k++) C[k] = 0.0f;
        if (m < M_TERMS) {
            float a = aarr[m], bb = barr[m], wm = w[m];
            float P[DEPTH + 1][DEPTH + 1];
            for (int L = 0; L <= DEPTH; L++)
                for (int k = 0; k <= DEPTH; k++) P[L][k] = 0.0f;
            P[0][0] = 1.0f;
            float coef1 = (a - bb) * 0.5f - (a + bb + 2.0f) * 0.5f * (l + r) / (r - l);
            float coef2 = (a + bb + 2.0f) / (r - l);
            float al0 = alphas[0 * M_TERMS + m];
            P[1][0] = al0 * coef1;
            P[1][1] = al0 * coef2;
            for (int L = 2; L <= DEPTH; L++) {
                float Lf = (float)L;
                float coef_l     = 2.0f * Lf * (Lf + a + bb) * (2.0f * Lf - 2.0f + a + bb);
                float coef_lm1_1 = (2.0f * Lf + a + bb - 1.0f) * (2.0f * Lf + a + bb) * (2.0f * Lf + a + bb - 2.0f);
                float coef_lm1_2 = (2.0f * Lf + a + bb - 1.0f) * (a * a - bb * bb);
                float coef_lm2   = 2.0f * (Lf - 1.0f + a) * (Lf - 1.0f + bb) * (2.0f * Lf + a + bb);
                float alL   = alphas[(L - 1) * M_TERMS + m];
                float alLm1 = alphas[(L - 2) * M_TERMS + m];
                float t1 = alL * (coef_lm1_1 / coef_l);
                float t2 = alL * (coef_lm1_2 / coef_l);
                float t3 = alL * alLm1 * (coef_lm2 / coef_l);
                float t1_2 = t1 * (2.0f / (r - l));
                float t2_2 = t1 * ((r + l) / (r - l)) + t2;
                for (int k = 0; k <= L; k++) {
                    float pm1 = (k > 0) ? P[L - 1][k - 1] : 0.0f;
                    P[L][k] = t1_2 * pm1 - t2_2 * P[L - 1][k] - t3 * P[L - 2][k];
                }
            }
            for (int L = 0; L <= DEPTH; L++)
                for (int k = 0; k <= L; k++) C[L * 4 + k] = wm * P[L][k];
        }
#pragma unroll
        for (int k = 0; k < 16; k++) {
            float v = C[k];
#pragma unroll
            for (int o = 16; o >= 1; o >>= 1)
                v += __shfl_xor_sync(0xFFFFFFFFu, v, o);
            if (m == 0) g_C[k] = v;
        }
    }
    gbar(0);

    // ======== P1a: block-local exclusive scan of degree counts ========
    if (blockIdx.x < SCAN_BLKS) {
        int node = blockIdx.x * NTHR + threadIdx.x;
        int lane = threadIdx.x & 31, wid = threadIdx.x >> 5;
        int v = (node < N_NODE) ? g_cnt[node] : 0;
        int incl = v;
#pragma unroll
        for (int o = 1; o < 32; o <<= 1) {
            int tv = __shfl_up_sync(0xFFFFFFFFu, incl, o);
            if (lane >= o) incl += tv;
        }
        if (lane == 31) wsum[wid] = incl;
        __syncthreads();
        if (threadIdx.x < 8) {
            int s = wsum[threadIdx.x];
#pragma unroll
            for (int o = 1; o < 8; o <<= 1) {
                int tv = __shfl_up_sync(0xFFu, s, o);
                if ((int)threadIdx.x >= o) s += tv;
            }
            wsum[threadIdx.x] = s;          // inclusive warp-prefix
        }
        __syncthreads();
        int bex = (wid > 0) ? wsum[wid - 1] : 0;
        if (node < N_NODE) g_rowptr[node] = bex + incl - v;     // block-local excl
        if (threadIdx.x == NTHR - 1) g_part[blockIdx.x] = bex + incl;  // block total
    }
    gbar(1);

    // ======== P1b: block 0 scans the 196 partials (exclusive, in place) ========
    if (blockIdx.x == 0) {
        int i = threadIdx.x;
        int lane = threadIdx.x & 31, wid = threadIdx.x >> 5;
        int v = (i < SCAN_BLKS) ? g_part[i] : 0;
        int incl = v;
#pragma unroll
        for (int o = 1; o < 32; o <<= 1) {
            int tv = __shfl_up_sync(0xFFFFFFFFu, incl, o);
            if (lane >= o) incl += tv;
        }
        if (lane == 31) wsum[wid] = incl;
        __syncthreads();
        if (threadIdx.x < 8) {
            int s = wsum[threadIdx.x];
#pragma unroll
            for (int o = 1; o < 8; o <<= 1) {
                int tv = __shfl_up_sync(0xFFu, s, o);
                if ((int)threadIdx.x >= o) s += tv;
            }
            wsum[threadIdx.x] = s;
        }
        __syncthreads();
        int bex = (wid > 0) ? wsum[wid - 1] : 0;
        if (i < SCAN_BLKS) g_part[i] = bex + incl - v;          // exclusive
    }
    gbar(2);

    // ======== P1c: finalize rowptr, dinv, reset cnt ========
    if (blockIdx.x < SCAN_BLKS) {
        int node = blockIdx.x * NTHR + threadIdx.x;
        if (node < N_NODE) {
            g_rowptr[node] += g_part[blockIdx.x];
            int v = g_cnt[node];
            float d = (v == 0) ? 1.0f : (float)v;
            g_dinv[node] = rsqrtf(d);
            g_cnt[node] = 0;                                    // restore invariant
        }
    }
    if (gtid == 0) g_rowptr[N_NODE] = N_EDGE;
    gbar(3);

    // ======== P2: fill CSR (no atomics; pos = rowptr[row] + rank) ========
    if (gtid < EQ4) {
        int t = gtid;
        int r0 = __ldg(&row[t]);
        int r1 = __ldg(&row[t + EQ4]);
        int r2 = __ldg(&row[t + 2 * EQ4]);
        int r3 = __ldg(&row[t + 3 * EQ4]);
        int c0 = __ldg(&col[t]);
        int c1 = __ldg(&col[t + EQ4]);
        int c2 = __ldg(&col[t + 2 * EQ4]);
        int c3 = __ldg(&col[t + 3 * EQ4]);
        float e0 = __ldg(&ea[t]);
        float e1 = __ldg(&ea[t + EQ4]);
        float e2 = __ldg(&ea[t + 2 * EQ4]);
        float e3 = __ldg(&ea[t + 3 * EQ4]);
        int k0 = __ldg(&g_rank[t]);
        int k1 = __ldg(&g_rank[t + EQ4]);
        int k2 = __ldg(&g_rank[t + 2 * EQ4]);
        int k3 = __ldg(&g_rank[t + 3 * EQ4]);
        float d0 = __ldg(&g_dinv[c0]);
        float d1 = __ldg(&g_dinv[c1]);
        float d2 = __ldg(&g_dinv[c2]);
        float d3 = __ldg(&g_dinv[c3]);
        int p0 = __ldg(&g_rowptr[r0]) + k0;
        int p1 = __ldg(&g_rowptr[r1]) + k1;
        int p2 = __ldg(&g_rowptr[r2]) + k2;
        int p3 = __ldg(&g_rowptr[r3]) + k3;
#define PACKV(vf)                                                             \
        ({ __half2 hv = __half2half2(__float2half_rn(vf)); *(int*)&hv; })
        g_epk[p0] = make_int2(c0, PACKV(e0 * d0));
        g_epk[p1] = make_int2(c1, PACKV(e1 * d1));
        g_epk[p2] = make_int2(c2, PACKV(e2 * d2));
        g_epk[p3] = make_int2(c3, PACKV(e3 * d3));
    }
    gbar(4);

    // ======== P3: spmm1  (xh -> yh[0]) ========
    for (int s = gtid; s < SPMM_SLOTS; s += TOT_THR) {
        int n = s >> 3;
        int c = (s & 7) << 3;
        int st = __ldg(&g_rowptr[n]);
        int en = __ldg(&g_rowptr[n + 1]);
        SPMM_GATHER(g_xh);
        size_t off = (size_t)n * D_FEAT + c;
        __half2 o0 = __floats2half2_rn(a0, a1);
        __half2 o1 = __floats2half2_rn(a2, a3);
        __half2 o2 = __floats2half2_rn(a4, a5);
        __half2 o3 = __floats2half2_rn(a6, a7);
        *(uint4*)(g_yh + off) = make_uint4(*(uint32_t*)&o0, *(uint32_t*)&o1,
                                           *(uint32_t*)&o2, *(uint32_t*)&o3);
    }
    gbar(5);

    // ======== P4: spmm2  (yh[0] -> yh[1]) ========
    for (int s = gtid; s < SPMM_SLOTS; s += TOT_THR) {
        int n = s >> 3;
        int c = (s & 7) << 3;
        int st = __ldg(&g_rowptr[n]);
        int en = __ldg(&g_rowptr[n + 1]);
        SPMM_GATHER(g_yh);
        size_t off = (size_t)n * D_FEAT + c;
        __half2 o0 = __floats2half2_rn(a0, a1);
        __half2 o1 = __floats2half2_rn(a2, a3);
        __half2 o2 = __floats2half2_rn(a4, a5);
        __half2 o3 = __floats2half2_rn(a6, a7);
        *(uint4*)(g_yh + (size_t)NF + off) =
            make_uint4(*(uint32_t*)&o0, *(uint32_t*)&o1,
                       *(uint32_t*)&o2, *(uint32_t*)&o3);
    }
    gbar(6);

    // ======== P5: spmm3 + epilogue ========
    for (int s = gtid; s < SPMM_SLOTS; s += TOT_THR) {
        int n = s >> 3;
        int c = (s & 7) << 3;
        int st = __ldg(&g_rowptr[n]);
        int en = __ldg(&g_rowptr[n + 1]);
        SPMM_GATHER(g_yh + NF);
        size_t off = (size_t)n * D_FEAT + c;
        float4 x0 = __ldg((const float4*)(x + off));
        float4 x1 = __ldg((const float4*)(x + off + 4));
        uint4 y1r = *(const uint4*)(g_yh + off);
        uint4 y2r = *(const uint4*)(g_yh + (size_t)NF + off);
        float2 p00 = __half22float2(*(__half2*)&y1r.x);
        float2 p01 = __half22float2(*(__half2*)&y1r.y);
        float2 p02 = __half22float2(*(__half2*)&y1r.z);
        float2 p03 = __half22float2(*(__half2*)&y1r.w);
        float2 q00 = __half22float2(*(__half2*)&y2r.x);
        float2 q01 = __half22float2(*(__half2*)&y2r.y);
        float2 q02 = __half22float2(*(__half2*)&y2r.z);
        float2 q03 = __half22float2(*(__half2*)&y2r.w);
        float* ob = out + (size_t)n * ((DEPTH + 1) * D_FEAT) + c;
#pragma unroll
        for (int L = 0; L <= DEPTH; L++) {
            float c0 = g_C[L * 4 + 0], c1 = g_C[L * 4 + 1];
            float c2 = g_C[L * 4 + 2], c3 = g_C[L * 4 + 3];
            float4 o;
            o.x = c0 * x0.x + c1 * p00.x + c2 * q00.x + c3 * a0;
            o.y = c0 * x0.y + c1 * p00.y + c2 * q00.y + c3 * a1;
            o.z = c0 * x0.z + c1 * p01.x + c2 * q01.x + c3 * a2;
            o.w = c0 * x0.w + c1 * p01.y + c2 * q01.y + c3 * a3;
            *(float4*)(ob + (size_t)L * D_FEAT) = o;
            float4 u;
            u.x = c0 * x1.x + c1 * p02.x + c2 * q02.x + c3 * a4;
            u.y = c0 * x1.y + c1 * p02.y + c2 * q02.y + c3 * a5;
            u.z = c0 * x1.z + c1 * p03.x + c2 * q03.x + c3 * a6;
            u.w = c0 * x1.w + c1 * p03.y + c2 * q03.y + c3 * a7;
            *(float4*)(ob + (size_t)L * D_FEAT + 4) = u;
        }
    }

    // ======== done: reset barrier counters for the next replay ========
    __syncthreads();
    if (threadIdx.x == 0) {
        __threadfence();
        atomicAdd((unsigned*)&g_done, 1u);
        if (blockIdx.x == 0) {
            while (g_done < (unsigned)NBLK) __nanosleep(64);
#pragma unroll
            for (int i = 0; i < 8; i++) g_ctr[i] = 0;
            g_done = 0;
            __threadfence();
        }
    }
}

// ---------------- launch: ONE kernel ----------------
extern "C" void kernel_launch(void* const* d_in, const int* in_sizes, int n_in,
                              void* d_out, int out_size) {
    const float* x      = (const float*)d_in[0];
    const int*   eidx   = (const int*)d_in[1];      // (2, N_EDGE): row then col
    const float* eattr  = (const float*)d_in[2];
    const float* alphas = (const float*)d_in[3];
    const float* w      = (const float*)d_in[4];
    const float* a_arr  = (const float*)d_in[5];
    const float* b_arr  = (const float*)d_in[6];
    float* out = (float*)d_out;

    const int* row = eidx;
    const int* col = eidx + N_EDGE;

    k_all<<<NBLK, NTHR>>>(row, col, eattr, x, alphas, w, a_arr, b_arr, out);
}